// round 17
// baseline (speedup 1.0000x reference)
#include <cuda_runtime.h>

#define TT 400000
#define HIDN 20
#define G4 80
#define INDIM 40

typedef unsigned int u32;
typedef unsigned long long u64;

// Static device scratch (no dynamic allocation allowed).
// g_pre0 layout: [t][unit u][gate s]  (s: 0=i,1=f,2=g,3=o)  -> 16B per (t,u)
__device__ float g_pre0[TT * G4];
__device__ float g_h1buf[TT * HIDN]; // h1 per step for the parallel output pass
__device__ float g_M[G4 * INDIM];    // fused (W_ih0 @ W_inp) [80,40] (gate-row order)
__device__ float g_b0[G4];           // fused layer-0 bias (gate-row order)
__device__ float g_b1[G4];           // b_ih1 + b_hh1       (gate-row order)

// ---------------------------------------------------------------------------
// Prep: fuse input projection into layer-0 input matmul.
// ---------------------------------------------------------------------------
__global__ void prep_kernel(const float* __restrict__ W_inp,
                            const float* __restrict__ b_inp,
                            const float* __restrict__ W_ih0,
                            const float* __restrict__ b_ih0,
                            const float* __restrict__ b_hh0,
                            const float* __restrict__ b_ih1,
                            const float* __restrict__ b_hh1) {
    int tid = threadIdx.x;
    if (tid < G4) {
        g_b1[tid] = b_ih1[tid] + b_hh1[tid];
        float s = b_ih0[tid] + b_hh0[tid];
        #pragma unroll
        for (int e = 0; e < HIDN; e++) s += W_ih0[tid * HIDN + e] * b_inp[e];
        g_b0[tid] = s;
    }
    for (int idx = tid; idx < G4 * INDIM; idx += blockDim.x) {
        int g = idx / INDIM, k = idx % INDIM;
        float s = 0.f;
        #pragma unroll
        for (int e = 0; e < HIDN; e++) s += W_ih0[g * HIDN + e] * W_inp[e * INDIM + k];
        g_M[idx] = s;
    }
}

// ---------------------------------------------------------------------------
// Parallel pass: pre0 for all T. Stores in [t][u][s] order (16B per unit).
// ---------------------------------------------------------------------------
__global__ __launch_bounds__(320) void pre0_kernel(const float* __restrict__ in_states) {
    __shared__ float sM[G4 * 41];
    __shared__ float sB[G4];
    __shared__ float sIn[4 * INDIM];
    int tid = threadIdx.x;
    for (int idx = tid; idx < G4 * INDIM; idx += 320)
        sM[(idx / INDIM) * 41 + (idx % INDIM)] = g_M[idx];
    if (tid < G4) sB[tid] = g_b0[tid];
    if (tid < 4 * INDIM) sIn[tid] = in_states[blockIdx.x * 4 * INDIM + tid];
    __syncthreads();

    int r = tid / G4;
    int g = tid % G4;    // gate-row index
    float acc = sB[g];
    #pragma unroll
    for (int k = 0; k < INDIM; k++) acc += sIn[r * INDIM + k] * sM[g * 41 + k];
    // reorder: gate row g -> unit u = g%20, section s = g/20
    g_pre0[(blockIdx.x * 4 + r) * G4 + (g % HIDN) * 4 + (g / HIDN)] = acc;
}

// ---------------------------------------------------------------------------
// Fast activations: ex2.approx + rcp.approx.
// ---------------------------------------------------------------------------
__device__ __forceinline__ float ex2f(float x) {
    float y; asm("ex2.approx.f32 %0, %1;" : "=f"(y) : "f"(x)); return y;
}
__device__ __forceinline__ float rcpf(float x) {
    float y; asm("rcp.approx.f32 %0, %1;" : "=f"(y) : "f"(x)); return y;
}
#define L2E 1.4426950408889634f
__device__ __forceinline__ float fast_sig(float a) {
    return rcpf(1.0f + ex2f(a * (-L2E)));
}
__device__ __forceinline__ float fast_tanh(float a) {
    return fmaf(rcpf(1.0f + ex2f(a * (-2.f * L2E))), 2.f, -1.f);
}

// ---- Packed f32x2 helpers (Blackwell FFMA2; only reachable via PTX) ----
__device__ __forceinline__ u64 ffma2(u64 a, u64 b, u64 c) {
    u64 d; asm("fma.rn.f32x2 %0, %1, %2, %3;" : "=l"(d) : "l"(a), "l"(b), "l"(c));
    return d;
}
__device__ __forceinline__ u64 add2(u64 a, u64 b) {
    u64 d; asm("add.rn.f32x2 %0, %1, %2;" : "=l"(d) : "l"(a), "l"(b));
    return d;
}
__device__ __forceinline__ u64 pack2(float lo, float hi) {
    u64 d; asm("mov.b64 %0, {%1, %2};" : "=l"(d) : "f"(lo), "f"(hi)); return d;
}
__device__ __forceinline__ float hsum2(u64 v) {
    float lo, hi; asm("mov.b64 {%0, %1}, %2;" : "=f"(lo), "=f"(hi) : "l"(v));
    return lo + hi;
}

__device__ __forceinline__ u32 smem_u32(const void* p) {
    return (u32)__cvta_generic_to_shared(p);
}
__device__ __forceinline__ void cp_async16(u32 dst, const float* src, int pred) {
    asm volatile(
        "{\n\t.reg .pred p;\n\tsetp.ne.u32 p, %2, 0;\n\t"
        "@p cp.async.ca.shared.global [%0], [%1], 16;\n\t}"
        :: "r"(dst), "l"(src), "r"(pred));
}
__device__ __forceinline__ int ld_acq(const int* p) {
    int v; asm volatile("ld.acquire.cta.shared.b32 %0, [%1];"
                        : "=r"(v) : "r"(smem_u32(p))); return v;
}
__device__ __forceinline__ void st_rel(int* p, int v) {
    asm volatile("st.release.cta.shared.b32 [%0], %1;"
                 :: "r"(smem_u32(p)), "r"(v));
}

#define PF_DIST 6     // cp.async prefetch distance; pre ring has 8 slots
#define COMPILER_FENCE() asm volatile("" ::: "memory")

// ---------------------------------------------------------------------------
// Serial recurrence: ONE WARP PER LAYER. 64 threads.
//   Warp 0 (L0): lane u (<20) owns unit u: all 4 gates as k-packed f32x2 dots.
//   Warp 1 (L1): same mapping, two input dots (wi1.h0 + wh1.h1).
//   No bar.sync, no shfl: gates are lane-local; intra-warp sync = __syncwarp.
//   h rings store PLAIN floats (h[0..19] contiguous); u64 reads of the ring
//   give consecutive pairs (h_{2j}, h_{2j+1}) matching the k-packed weights.
//   Cross-warp: release/acquire progress flags with cached checks.
// ---------------------------------------------------------------------------
__global__ __launch_bounds__(64, 1) void lstm_seq_kernel(
        const float* __restrict__ W_hh0,
        const float* __restrict__ W_ih1,
        const float* __restrict__ W_hh1,
        float* __restrict__ out_tail)   // d_out + TT : [h0(20), h1(20), c0(20), c1(20)]
{
    __shared__ __align__(16) float hbuf0[8][HIDN];    // h0(s) at slot s&7
    __shared__ __align__(16) float hbuf1[2][HIDN];    // h1(s) at slot s&1
    __shared__ __align__(16) float4 sh_pre[8][HIDN];  // pre0 cp.async ring
    __shared__ int s_prog[2];                          // [0]=L0 step, [1]=L1 step

    const int tid  = threadIdx.x;
    const int lane = tid & 31;
    const bool isL0 = (tid < 32);
    const int u    = (lane < HIDN) ? lane : 0;   // lanes 20..31: harmless dupes
    const bool act_lane = (lane < HIDN);

    // Per-lane packed weights: 4 gate rows (i,f,g,o), k packed in pairs.
    u64 wA[4][10];                  // L0: W_hh0 rows ; L1: W_ih1 rows
    u64 wB[4][10];                  // L1 only: W_hh1 rows
    float4 b1v = make_float4(0.f, 0.f, 0.f, 0.f);
    if (isL0) {
        #pragma unroll
        for (int s = 0; s < 4; s++) {
            const float* row = &W_hh0[(s * HIDN + u) * HIDN];
            #pragma unroll
            for (int j = 0; j < 10; j++)
                wA[s][j] = pack2(__ldg(&row[2 * j]), __ldg(&row[2 * j + 1]));
        }
    } else {
        #pragma unroll
        for (int s = 0; s < 4; s++) {
            const float* rA = &W_ih1[(s * HIDN + u) * HIDN];
            const float* rB = &W_hh1[(s * HIDN + u) * HIDN];
            #pragma unroll
            for (int j = 0; j < 10; j++) {
                wA[s][j] = pack2(__ldg(&rA[2 * j]), __ldg(&rA[2 * j + 1]));
                wB[s][j] = pack2(__ldg(&rB[2 * j]), __ldg(&rB[2 * j + 1]));
            }
        }
        b1v = make_float4(g_b1[u], g_b1[HIDN + u], g_b1[2 * HIDN + u], g_b1[3 * HIDN + u]);
    }

    const u32 spre = smem_u32(&sh_pre[0][0]);
    const int do_cp = isL0 && act_lane;

    // cp.async pipeline prologue: queue pre0 for steps 1..PF_DIST.
    if (isL0) {
        #pragma unroll
        for (int j = 1; j <= PF_DIST; j++) {
            cp_async16(spre + (u32)(((j & 7) * HIDN + u) * 16),
                       &g_pre0[j * G4 + u * 4], do_cp);
            asm volatile("cp.async.commit_group;");
        }
    }

    if (tid < HIDN) {
        hbuf1[0][tid] = 0.f;
        hbuf1[1][tid] = 0.f;
    }
    if (tid == 0) { s_prog[0] = -1; s_prog[1] = 0; }
    __syncthreads();   // one-time: init visible to both warps

    if (isL0) {
        // ================= Layer-0 warp =================
        float c0 = 0.f, h0r = 0.f;
        int cprog1 = 0;

        // t = 0: h0(-1)=0 -> preact = pre0 directly.
        {
            float4 pv = *(const float4*)&g_pre0[u * 4];
            float iv = fast_sig(pv.x);
            float gv = fast_tanh(pv.z);
            float ov = fast_sig(pv.w);
            c0  = iv * gv;
            h0r = ov * fast_tanh(c0);
            if (act_lane) hbuf0[0][u] = h0r;
            __syncwarp();
            if (lane == 0) st_rel(&s_prog[0], 0);
        }

        for (int t = 1; t < TT; t++) {
            // Back-pressure: slot t&7 is read by L1 at its iteration t-7.
            if (cprog1 < t - 7) {
                cprog1 = ld_acq(&s_prog[1]);
                while (cprog1 < t - 7) { __nanosleep(32); cprog1 = ld_acq(&s_prog[1]); }
            }
            COMPILER_FENCE();

            int tp = t + PF_DIST;
            cp_async16(spre + (u32)(((tp & 7) * HIDN + u) * 16),
                       &g_pre0[tp * G4 + u * 4], do_cp & (tp < TT));
            asm volatile("cp.async.commit_group;");

            const u64* hp = (const u64*)&hbuf0[(t - 1) & 7][0];  // pairs (h2j, h2j+1)

            asm volatile("cp.async.wait_group 6;");
            float4 pv = sh_pre[t & 7][u];

            u64 ai = pack2(pv.x, 0.f), af = pack2(pv.y, 0.f);
            u64 ag = pack2(pv.z, 0.f), ao = pack2(pv.w, 0.f);
            #pragma unroll
            for (int j = 0; j < 10; j++) {
                u64 h = hp[j];
                ai = ffma2(wA[0][j], h, ai);
                af = ffma2(wA[1][j], h, af);
                ag = ffma2(wA[2][j], h, ag);
                ao = ffma2(wA[3][j], h, ao);
            }
            float iv = fast_sig(hsum2(ai));
            float fv = fast_sig(hsum2(af));
            float gv = fast_tanh(hsum2(ag));
            float ov = fast_sig(hsum2(ao));

            c0  = fmaf(fv, c0, iv * gv);
            h0r = ov * fast_tanh(c0);
            if (act_lane) hbuf0[t & 7][u] = h0r;    // publish h0(t)
            __syncwarp();
            if (lane == 0) st_rel(&s_prog[0], t);   // release
        }

        if (act_lane) {
            out_tail[u]            = h0r;   // h_n layer 0
            out_tail[2 * HIDN + u] = c0;    // c_n layer 0
        }
    } else {
        // ================= Layer-1 warp =================
        float c1 = 0.f, h1r = 0.f;
        int cprog0 = -1;

        for (int t = 1; t <= TT; t++) {
            // Need h0(t-1): wait until L0 published step t-1 (cached check).
            if (cprog0 < t - 1) {
                cprog0 = ld_acq(&s_prog[0]);
                while (cprog0 < t - 1) { __nanosleep(16); cprog0 = ld_acq(&s_prog[0]); }
            }
            COMPILER_FENCE();

            const u64* hp0 = (const u64*)&hbuf0[(t - 1) & 7][0];  // h0(t-1)
            const u64* hp1 = (const u64*)&hbuf1[t & 1][0];        // h1(t-2)

            u64 qa0 = pack2(b1v.x, 0.f), qa1 = pack2(b1v.y, 0.f);
            u64 qa2 = pack2(b1v.z, 0.f), qa3 = pack2(b1v.w, 0.f);
            u64 qb0 = 0ULL, qb1 = 0ULL, qb2 = 0ULL, qb3 = 0ULL;
            #pragma unroll
            for (int j = 0; j < 10; j++) {
                u64 h0j = hp0[j];
                u64 h1j = hp1[j];
                qa0 = ffma2(wA[0][j], h0j, qa0);
                qa1 = ffma2(wA[1][j], h0j, qa1);
                qa2 = ffma2(wA[2][j], h0j, qa2);
                qa3 = ffma2(wA[3][j], h0j, qa3);
                qb0 = ffma2(wB[0][j], h1j, qb0);
                qb1 = ffma2(wB[1][j], h1j, qb1);
                qb2 = ffma2(wB[2][j], h1j, qb2);
                qb3 = ffma2(wB[3][j], h1j, qb3);
            }
            float iv = fast_sig(hsum2(add2(qa0, qb0)));
            float fv = fast_sig(hsum2(add2(qa1, qb1)));
            float gv = fast_tanh(hsum2(add2(qa2, qb2)));
            float ov = fast_sig(hsum2(add2(qa3, qb3)));

            c1  = fmaf(fv, c1, iv * gv);
            h1r = ov * fast_tanh(c1);
            if (act_lane) {
                hbuf1[(t - 1) & 1][u] = h1r;         // publish h1(t-1)
                g_h1buf[(t - 1) * HIDN + u] = h1r;
            }
            __syncwarp();
            if (lane == 0) st_rel(&s_prog[1], t);     // slot (t-1)&7 consumed
        }

        if (act_lane) {
            out_tail[HIDN + u]     = h1r;   // h_n layer 1
            out_tail[3 * HIDN + u] = c1;    // c_n layer 1
        }
    }
}

// ---------------------------------------------------------------------------
// Parallel output pass: out[t] = h1[t] . W_out + b_out
// ---------------------------------------------------------------------------
__global__ void out_kernel(const float* __restrict__ W_out,
                           const float* __restrict__ b_out,
                           float* __restrict__ out) {
    int t = blockIdx.x * blockDim.x + threadIdx.x;
    if (t >= TT) return;
    float wv[HIDN];
    #pragma unroll
    for (int k = 0; k < HIDN; k++) wv[k] = __ldg(&W_out[k]);
    const float4* h4 = reinterpret_cast<const float4*>(&g_h1buf[t * HIDN]);
    float acc = __ldg(b_out);
    #pragma unroll
    for (int i = 0; i < 5; i++) {
        float4 v = __ldg(&h4[i]);
        acc += wv[4 * i] * v.x + wv[4 * i + 1] * v.y
             + wv[4 * i + 2] * v.z + wv[4 * i + 3] * v.w;
    }
    out[t] = acc;
}

extern "C" void kernel_launch(void* const* d_in, const int* in_sizes, int n_in,
                              void* d_out, int out_size) {
    const float* in_states = (const float*)d_in[0];
    const float* W_inp     = (const float*)d_in[1];
    const float* b_inp     = (const float*)d_in[2];
    const float* W_ih0     = (const float*)d_in[3];
    const float* W_hh0     = (const float*)d_in[4];
    const float* b_ih0     = (const float*)d_in[5];
    const float* b_hh0     = (const float*)d_in[6];
    const float* W_ih1     = (const float*)d_in[7];
    const float* W_hh1     = (const float*)d_in[8];
    const float* b_ih1     = (const float*)d_in[9];
    const float* b_hh1     = (const float*)d_in[10];
    const float* W_out     = (const float*)d_in[11];
    const float* b_out     = (const float*)d_in[12];
    float* out = (float*)d_out;

    prep_kernel<<<1, 128>>>(W_inp, b_inp, W_ih0, b_ih0, b_hh0, b_ih1, b_hh1);
    pre0_kernel<<<TT / 4, 320>>>(in_states);
    lstm_seq_kernel<<<1, 64>>>(W_hh0, W_ih1, W_hh1, out + TT);
    out_kernel<<<(TT + 255) / 256, 256>>>(W_out, b_out, out);
}